// round 14
// baseline (speedup 1.0000x reference)
#include <cuda_runtime.h>
#include <cuda_fp16.h>
#include <cstddef>

#define NN_MAX 50000
#define EE_MAX 1600000
#define SCAN_B 1024
#define NB_MAX 64

// -------- scratch (device globals; no allocation allowed) --------
__device__ __align__(16) float  g_dis[NN_MAX];
__device__ int    g_cnt[NN_MAX];      // zeroed at END of each launch (final_agg_k)
__device__ int    g_off[NN_MAX + 1];
__device__ int    g_sl[NN_MAX];
__device__ int    g_bsum[NB_MAX];
__device__ __align__(16) int g_slot[EE_MAX];
__device__ __align__(16) int g_csr[EE_MAX];
__device__ __align__(16) __half g_h16[(size_t)NN_MAX * 128];  // post-GEMM, pre-scaled
__device__ __align__(16) __half g_a16[(size_t)NN_MAX * 128];  // post-agg activations
__device__ float  g_t[NN_MAX];
// W1/W2/W3 pre-converted to fp16 in MMA layout: [64 kpairs][128 cols] half2,
// w16[kp*128 + c] = (W[2kp][c], W[2kp+1][c])
__device__ __align__(16) __half2 g_W16[3][64 * 128];

// ---------------- helpers ----------------
__device__ __forceinline__ float4 h8_to_f4(float2 raw) {
    __half2 ha = *reinterpret_cast<__half2*>(&raw.x);
    __half2 hb = *reinterpret_cast<__half2*>(&raw.y);
    float2 fa = __half22float2(ha), fb = __half22float2(hb);
    return make_float4(fa.x, fa.y, fb.x, fb.y);
}
__device__ __forceinline__ float2 f4_to_h8(float x, float y, float z, float w) {
    __half2 h0 = __floats2half2_rn(x, y), h1 = __floats2half2_rn(z, w);
    float2 o;
    o.x = *reinterpret_cast<float*>(&h0);
    o.y = *reinterpret_cast<float*>(&h1);
    return o;
}
__device__ __forceinline__ float4 pairsum_f4(float2 ra, float2 rb) {
    __half2 alo = *reinterpret_cast<__half2*>(&ra.x);
    __half2 ahi = *reinterpret_cast<__half2*>(&ra.y);
    __half2 blo = *reinterpret_cast<__half2*>(&rb.x);
    __half2 bhi = *reinterpret_cast<__half2*>(&rb.y);
    __half2 slo = __hadd2(alo, blo);
    __half2 shi = __hadd2(ahi, bhi);
    float2 fa = __half22float2(slo), fb = __half22float2(shi);
    return make_float4(fa.x, fa.y, fb.x, fb.y);
}

// ---------------- W pre-conversion: fp32 [128][128] -> half2 pair layout ------
__global__ void conv_w_k(const float* __restrict__ W, int slot) {
    int i = blockIdx.x * blockDim.x + threadIdx.x;   // 0..8191
    if (i >= 64 * 128) return;
    int kp = i >> 7;
    int c  = i & 127;
    g_W16[slot][i] = __floats2half2_rn(W[(2 * kp) * 128 + c], W[(2 * kp + 1) * 128 + c]);
}

// ---------------- graph preprocessing ----------------
__global__ void hist_dst_k(const int* __restrict__ ei, int E) {
    int t = blockIdx.x * blockDim.x + threadIdx.x;
    int e = t * 4;
    if (e + 3 < E) {
        int4 d = *(const int4*)(ei + E + e);
        int p0 = atomicAdd(&g_cnt[d.x], 1);
        int p1 = atomicAdd(&g_cnt[d.y], 1);
        int p2 = atomicAdd(&g_cnt[d.z], 1);
        int p3 = atomicAdd(&g_cnt[d.w], 1);
        *(int4*)(g_slot + e) = make_int4(p0, p1, p2, p3);
    } else {
        for (; e < E; e++) g_slot[e] = atomicAdd(&g_cnt[ei[E + e]], 1);
    }
}

__global__ void dis_k(int n) {
    int i = blockIdx.x * blockDim.x + threadIdx.x;
    if (i < n) g_dis[i] = rsqrtf(1.0f + (float)g_cnt[i]);
}

__global__ void scan1_k(int n) {
    __shared__ int sh[SCAN_B];
    int t = threadIdx.x;
    int i = blockIdx.x * SCAN_B + t;
    int v = (i < n) ? g_cnt[i] : 0;
    sh[t] = v;
    __syncthreads();
    for (int d = 1; d < SCAN_B; d <<= 1) {
        int u = (t >= d) ? sh[t - d] : 0;
        __syncthreads();
        sh[t] += u;
        __syncthreads();
    }
    if (i < n) g_sl[i] = sh[t] - v;
    if (t == SCAN_B - 1) g_bsum[blockIdx.x] = sh[t];
}

__global__ void scan3_k(int n, int nb) {
    __shared__ int sh[NB_MAX];
    int t = threadIdx.x;
    if (t < NB_MAX) sh[t] = (t < nb) ? g_bsum[t] : 0;
    __syncthreads();
    for (int d = 1; d < NB_MAX; d <<= 1) {
        int u = (t < NB_MAX && t >= d) ? sh[t - d] : 0;
        __syncthreads();
        if (t < NB_MAX) sh[t] += u;
        __syncthreads();
    }
    int i = blockIdx.x * blockDim.x + t;
    if (i >= n) return;
    int bidx = i >> 10;
    int boff = (bidx > 0) ? sh[bidx - 1] : 0;
    int off = g_sl[i] + boff;
    g_off[i] = off;
    if (i == n - 1) g_off[n] = off + g_cnt[i];
}

__global__ void build_csr_k(const int* __restrict__ ei, int E) {
    int t = blockIdx.x * blockDim.x + threadIdx.x;
    int e = t * 4;
    if (e + 3 < E) {
        int4 s  = *(const int4*)(ei + e);
        int4 d  = *(const int4*)(ei + E + e);
        int4 sl = *(const int4*)(g_slot + e);
        g_csr[g_off[d.x] + sl.x] = s.x;
        g_csr[g_off[d.y] + sl.y] = s.y;
        g_csr[g_off[d.z] + sl.z] = s.z;
        g_csr[g_off[d.w] + sl.w] = s.w;
    } else {
        for (; e < E; e++) g_csr[g_off[ei[E + e]] + g_slot[e]] = ei[e];
    }
}

// ---------------- fp16 tensor-core GEMM: g_h16[M,:] = dis[row] * (A @ W) ------
// 128-row tiles, 256 threads (8 warps: 4M x 2N), warp tile 32x64, mma.m16n8k16.
// K chunked by 64. W read from g_W16[wslot] (pre-converted pair layout) -> pure copy.
__global__ __launch_bounds__(256, 2)
void gemm_fp16_k(const float* __restrict__ Ax, int wslot, int M, int use_ga)
{
    __shared__ __align__(16) __half2 As2[128][36];
    __shared__ __align__(16) __half2 Bs2[32][136];

    int tid  = threadIdx.x;
    int wid  = tid >> 5;
    int lane = tid & 31;
    int g    = lane >> 2;
    int tig  = lane & 3;
    int warp_m = wid & 3;
    int warp_n = wid >> 2;
    int row0 = blockIdx.x * 128;
    const __half2* __restrict__ Wp = g_W16[wslot];

    float acc[2][8][4];
#pragma unroll
    for (int mf = 0; mf < 2; mf++)
#pragma unroll
        for (int nf = 0; nf < 8; nf++)
#pragma unroll
            for (int i = 0; i < 4; i++) acc[mf][nf][i] = 0.f;

    for (int kb = 0; kb < 128; kb += 64) {
        if (use_ga) {
            // fp16 A: 128 rows x 64 halves = 1024 16B chunks, 4 passes
            const __half* A16 = g_a16;
#pragma unroll
            for (int l = 0; l < 4; l++) {
                int idx = tid + l * 256;
                int r  = idx >> 3;
                int c8 = idx & 7;
                int gr = row0 + r;
                if (gr > M - 1) gr = M - 1;
                float4 raw = *(const float4*)(A16 + (size_t)gr * 128 + kb + c8 * 8);
                *(float4*)(&As2[r][c8 * 4]) = raw;
            }
        } else {
            // fp32 A: 128 rows x 16 float4 = 2048 tasks, 8 passes
#pragma unroll
            for (int l = 0; l < 8; l++) {
                int idx = tid + l * 256;
                int r  = idx >> 4;
                int c4 = idx & 15;
                int gr = row0 + r;
                if (gr > M - 1) gr = M - 1;
                float4 v = *(const float4*)(Ax + (size_t)gr * 128 + kb + c4 * 4);
                As2[r][c4 * 2]     = __floats2half2_rn(v.x, v.y);
                As2[r][c4 * 2 + 1] = __floats2half2_rn(v.z, v.w);
            }
        }
        // W chunk: 32 kpairs x 32 col-groups = 1024 float4 copies, 4 passes
        int kp0 = kb >> 1;
#pragma unroll
        for (int l = 0; l < 4; l++) {
            int idx = tid + l * 256;
            int r  = idx >> 5;                    // kpair 0..31
            int c4 = idx & 31;
            float4 v = *(const float4*)(Wp + (size_t)(kp0 + r) * 128 + c4 * 4);
            *(float4*)(&Bs2[r][c4 * 4]) = v;
        }
        __syncthreads();

#pragma unroll
        for (int ks = 0; ks < 4; ks++) {
            int k0 = ks * 8;
            unsigned a[2][4];
#pragma unroll
            for (int mf = 0; mf < 2; mf++) {
                int rb = warp_m * 32 + mf * 16 + g;
                a[mf][0] = *(unsigned*)&As2[rb][k0 + tig];
                a[mf][1] = *(unsigned*)&As2[rb + 8][k0 + tig];
                a[mf][2] = *(unsigned*)&As2[rb][k0 + tig + 4];
                a[mf][3] = *(unsigned*)&As2[rb + 8][k0 + tig + 4];
            }
            unsigned b[8][2];
#pragma unroll
            for (int nf = 0; nf < 8; nf++) {
                int cb = warp_n * 64 + nf * 8 + g;
                b[nf][0] = *(unsigned*)&Bs2[k0 + tig][cb];
                b[nf][1] = *(unsigned*)&Bs2[k0 + tig + 4][cb];
            }
#pragma unroll
            for (int mf = 0; mf < 2; mf++)
#pragma unroll
                for (int nf = 0; nf < 8; nf++) {
                    asm volatile(
                        "mma.sync.aligned.m16n8k16.row.col.f32.f16.f16.f32 "
                        "{%0,%1,%2,%3}, {%4,%5,%6,%7}, {%8,%9}, {%0,%1,%2,%3};"
                        : "+f"(acc[mf][nf][0]), "+f"(acc[mf][nf][1]),
                          "+f"(acc[mf][nf][2]), "+f"(acc[mf][nf][3])
                        : "r"(a[mf][0]), "r"(a[mf][1]), "r"(a[mf][2]), "r"(a[mf][3]),
                          "r"(b[nf][0]), "r"(b[nf][1]));
                }
        }
        __syncthreads();
    }

    // epilogue: scale by rsqrt(1+cnt[row]) computed inline, write fp16
#pragma unroll
    for (int mf = 0; mf < 2; mf++) {
        int rb = row0 + warp_m * 32 + mf * 16 + g;
        float d0 = (rb < M)     ? rsqrtf(1.0f + (float)g_cnt[rb])     : 0.f;
        float d1 = (rb + 8 < M) ? rsqrtf(1.0f + (float)g_cnt[rb + 8]) : 0.f;
#pragma unroll
        for (int nf = 0; nf < 8; nf++) {
            int col = warp_n * 64 + nf * 8 + tig * 2;
            if (rb < M) {
                __half2 v = __floats2half2_rn(d0 * acc[mf][nf][0], d0 * acc[mf][nf][1]);
                *(__half2*)(g_h16 + (size_t)rb * 128 + col) = v;
            }
            if (rb + 8 < M) {
                __half2 v = __floats2half2_rn(d1 * acc[mf][nf][2], d1 * acc[mf][nf][3]);
                *(__half2*)(g_h16 + (size_t)(rb + 8) * 128 + col) = v;
            }
        }
    }
}

// ---------------- aggregation: warp per node, pure gather+add ----------------
__global__ void agg128_k(const float* __restrict__ b, int M,
                         const float* __restrict__ W4)
{
    int w = (blockIdx.x * blockDim.x + threadIdx.x) >> 5;
    if (w >= M) return;
    int lane = threadIdx.x & 31;
    const __half* __restrict__ h = g_h16;
    int beg = g_off[w], end = g_off[w + 1];
    float dv = g_dis[w];

    float ax = 0.f, ay = 0.f, az = 0.f, aw = 0.f;
    int e = beg;
    for (; e < end && (e & 3); e++) {
        int s0 = g_csr[e];
        float4 h0 = h8_to_f4(((const float2*)(h + (size_t)s0 * 128))[lane]);
        ax += h0.x; ay += h0.y; az += h0.z; aw += h0.w;
    }
    for (; e + 8 <= end; e += 8) {
        int4 i0 = *(const int4*)(g_csr + e);
        int4 i1 = *(const int4*)(g_csr + e + 4);
        float2 r0 = ((const float2*)(h + (size_t)i0.x * 128))[lane];
        float2 r1 = ((const float2*)(h + (size_t)i0.y * 128))[lane];
        float2 r2 = ((const float2*)(h + (size_t)i0.z * 128))[lane];
        float2 r3 = ((const float2*)(h + (size_t)i0.w * 128))[lane];
        float2 r4 = ((const float2*)(h + (size_t)i1.x * 128))[lane];
        float2 r5 = ((const float2*)(h + (size_t)i1.y * 128))[lane];
        float2 r6 = ((const float2*)(h + (size_t)i1.z * 128))[lane];
        float2 r7 = ((const float2*)(h + (size_t)i1.w * 128))[lane];
        float4 p0 = pairsum_f4(r0, r1);
        float4 p1 = pairsum_f4(r2, r3);
        float4 p2 = pairsum_f4(r4, r5);
        float4 p3 = pairsum_f4(r6, r7);
        ax += (p0.x + p1.x) + (p2.x + p3.x);
        ay += (p0.y + p1.y) + (p2.y + p3.y);
        az += (p0.z + p1.z) + (p2.z + p3.z);
        aw += (p0.w + p1.w) + (p2.w + p3.w);
    }
    for (; e < end; e++) {
        int s0 = g_csr[e];
        float4 h0 = h8_to_f4(((const float2*)(h + (size_t)s0 * 128))[lane]);
        ax += h0.x; ay += h0.y; az += h0.z; aw += h0.w;
    }

    float4 hs = h8_to_f4(((const float2*)(h + (size_t)w * 128))[lane]);
    float4 bb = ((const float4*)b)[lane];
    float rx = fmaxf(dv * (ax + hs.x) + bb.x, 0.f);
    float ry = fmaxf(dv * (ay + hs.y) + bb.y, 0.f);
    float rz = fmaxf(dv * (az + hs.z) + bb.z, 0.f);
    float rw = fmaxf(dv * (aw + hs.w) + bb.w, 0.f);

    if (W4 == nullptr) {
        ((float2*)(g_a16 + (size_t)w * 128))[lane] = f4_to_h8(rx, ry, rz, rw);
    } else {
        float4 wv = ((const float4*)W4)[lane];
        float s = rx * wv.x + ry * wv.y + rz * wv.z + rw * wv.w;
#pragma unroll
        for (int o = 16; o; o >>= 1) s += __shfl_xor_sync(0xFFFFFFFFu, s, o);
        if (lane == 0) g_t[w] = dv * s;
    }
}

// warp per node: lanes gather edges in parallel, shfl reduce.
// also re-zeroes g_cnt for the next launch (graph replay invariant).
__global__ void final_agg_k(const float* __restrict__ b4, float* __restrict__ out, int M)
{
    int w = (blockIdx.x * blockDim.x + threadIdx.x) >> 5;
    if (w >= M) return;
    int lane = threadIdx.x & 31;
    int beg = g_off[w], end = g_off[w + 1];
    float s = 0.f;
    for (int e = beg + lane; e < end; e += 32) s += g_t[g_csr[e]];
#pragma unroll
    for (int o = 16; o; o >>= 1) s += __shfl_xor_sync(0xFFFFFFFFu, s, o);
    if (lane == 0) out[w] = g_dis[w] * (s + g_t[w]) + b4[0];
    if (lane == 1) g_cnt[w] = 0;   // leave zeroed for next launch
}

// ---------------- launch ----------------
extern "C" void kernel_launch(void* const* d_in, const int* in_sizes, int n_in,
                              void* d_out, int out_size)
{
    const float* x  = (const float*)d_in[0];
    const int*   ei = (const int*)d_in[1];
    const float* W1 = (const float*)d_in[2]; const float* b1 = (const float*)d_in[3];
    const float* W2 = (const float*)d_in[4]; const float* b2 = (const float*)d_in[5];
    const float* W3 = (const float*)d_in[6]; const float* b3 = (const float*)d_in[7];
    const float* W4 = (const float*)d_in[8]; const float* b4 = (const float*)d_in[9];

    int N = in_sizes[0] / 128;   // 50000
    int E = in_sizes[1] / 2;     // 1600000
    float* out = (float*)d_out;

    int nb = (N + SCAN_B - 1) / SCAN_B;

    static cudaStream_t s2 = nullptr;
    static cudaEvent_t ev_fork, ev_cnt, ev_csr;
    if (s2 == nullptr) {
        cudaStreamCreateWithFlags(&s2, cudaStreamNonBlocking);
        cudaEventCreateWithFlags(&ev_fork, cudaEventDisableTiming);
        cudaEventCreateWithFlags(&ev_cnt,  cudaEventDisableTiming);
        cudaEventCreateWithFlags(&ev_csr,  cudaEventDisableTiming);
    }

    // fork: graph preprocessing on s2 (g_cnt is already zero — invariant)
    cudaEventRecord(ev_fork, 0);
    cudaStreamWaitEvent(s2, ev_fork, 0);
    hist_dst_k <<<(E / 4 + 255) / 256, 256, 0, s2>>>(ei, E);
    cudaEventRecord(ev_cnt, s2);
    dis_k      <<<(N + 255) / 256, 256, 0, s2>>>(N);
    scan1_k    <<<nb, SCAN_B, 0, s2>>>(N);
    scan3_k    <<<(N + 255) / 256, 256, 0, s2>>>(N, nb);
    build_csr_k<<<(E / 4 + 255) / 256, 256, 0, s2>>>(ei, E);
    cudaEventRecord(ev_csr, s2);

    // main stream: W conversions run concurrent with hist on s2
    conv_w_k<<<32, 256>>>(W1, 0);
    conv_w_k<<<32, 256>>>(W2, 1);
    conv_w_k<<<32, 256>>>(W3, 2);

    int gemm_blocks = (N + 127) / 128;          // 391
    int agg_blocks  = (N * 32 + 255) / 256;

    // GEMM-1 needs g_cnt (epilogue) + g_W16[0]: overlaps dis/scan/build_csr on s2
    cudaStreamWaitEvent(0, ev_cnt, 0);
    gemm_fp16_k<<<gemm_blocks, 256>>>(x, 0, N, 0);
    cudaStreamWaitEvent(0, ev_csr, 0);
    agg128_k   <<<agg_blocks, 256>>>(b1, N, nullptr);

    gemm_fp16_k<<<gemm_blocks, 256>>>(x, 1, N, 1);
    agg128_k   <<<agg_blocks, 256>>>(b2, N, nullptr);

    gemm_fp16_k<<<gemm_blocks, 256>>>(x, 2, N, 1);
    agg128_k   <<<agg_blocks, 256>>>(b3, N, W4);

    final_agg_k<<<agg_blocks, 256>>>(b4, out, N);
}

// round 15
// speedup vs baseline: 1.0224x; 1.0224x over previous
#include <cuda_runtime.h>
#include <cuda_fp16.h>
#include <cstddef>

#define NN_MAX 50000
#define EE_MAX 1600000
#define SCAN_B 1024
#define NB_MAX 64

// -------- scratch (device globals; no allocation allowed) --------
__device__ __align__(16) float  g_dis[NN_MAX];
__device__ int    g_cnt[NN_MAX];      // zeroed at END of each launch (final_agg_k)
__device__ int    g_off[NN_MAX + 1];
__device__ int    g_sl[NN_MAX];
__device__ int    g_bsum[NB_MAX];
__device__ __align__(16) int g_slot[EE_MAX];
__device__ __align__(16) int g_csr[EE_MAX];
__device__ __align__(16) __half g_h16[(size_t)NN_MAX * 128];  // post-GEMM, pre-scaled
__device__ __align__(16) __half g_a16[(size_t)NN_MAX * 128];  // post-agg activations
__device__ float  g_t[NN_MAX];

// ---------------- helpers ----------------
__device__ __forceinline__ float4 h8_to_f4(float2 raw) {
    __half2 ha = *reinterpret_cast<__half2*>(&raw.x);
    __half2 hb = *reinterpret_cast<__half2*>(&raw.y);
    float2 fa = __half22float2(ha), fb = __half22float2(hb);
    return make_float4(fa.x, fa.y, fb.x, fb.y);
}
__device__ __forceinline__ float2 f4_to_h8(float x, float y, float z, float w) {
    __half2 h0 = __floats2half2_rn(x, y), h1 = __floats2half2_rn(z, w);
    float2 o;
    o.x = *reinterpret_cast<float*>(&h0);
    o.y = *reinterpret_cast<float*>(&h1);
    return o;
}
__device__ __forceinline__ float4 pairsum_f4(float2 ra, float2 rb) {
    __half2 alo = *reinterpret_cast<__half2*>(&ra.x);
    __half2 ahi = *reinterpret_cast<__half2*>(&ra.y);
    __half2 blo = *reinterpret_cast<__half2*>(&rb.x);
    __half2 bhi = *reinterpret_cast<__half2*>(&rb.y);
    __half2 slo = __hadd2(alo, blo);
    __half2 shi = __hadd2(ahi, bhi);
    float2 fa = __half22float2(slo), fb = __half22float2(shi);
    return make_float4(fa.x, fa.y, fb.x, fb.y);
}

// ---------------- graph preprocessing ----------------
__global__ void hist_dst_k(const int* __restrict__ ei, int E) {
    int t = blockIdx.x * blockDim.x + threadIdx.x;
    int e = t * 4;
    if (e + 3 < E) {
        int4 d = *(const int4*)(ei + E + e);
        int p0 = atomicAdd(&g_cnt[d.x], 1);
        int p1 = atomicAdd(&g_cnt[d.y], 1);
        int p2 = atomicAdd(&g_cnt[d.z], 1);
        int p3 = atomicAdd(&g_cnt[d.w], 1);
        *(int4*)(g_slot + e) = make_int4(p0, p1, p2, p3);
    } else {
        for (; e < E; e++) g_slot[e] = atomicAdd(&g_cnt[ei[E + e]], 1);
    }
}

// block-local scan + per-block totals + dis (fused)
__global__ void scan1_k(int n) {
    __shared__ int sh[SCAN_B];
    int t = threadIdx.x;
    int i = blockIdx.x * SCAN_B + t;
    int v = (i < n) ? g_cnt[i] : 0;
    sh[t] = v;
    __syncthreads();
    for (int d = 1; d < SCAN_B; d <<= 1) {
        int u = (t >= d) ? sh[t - d] : 0;
        __syncthreads();
        sh[t] += u;
        __syncthreads();
    }
    if (i < n) {
        g_sl[i] = sh[t] - v;
        g_dis[i] = rsqrtf(1.0f + (float)v);
    }
    if (t == SCAN_B - 1) g_bsum[blockIdx.x] = sh[t];
}

// fused scan3 + build_csr: each block scans the <=64 block totals in smem;
// off(d) = g_sl[d] + bprefix[d>>10]. First N threads also write g_off.
__global__ void finalize_k(const int* __restrict__ ei, int E, int n, int nb) {
    __shared__ int sh[NB_MAX];
    int t = threadIdx.x;
    if (t < NB_MAX) sh[t] = (t < nb) ? g_bsum[t] : 0;
    __syncthreads();
    for (int d = 1; d < NB_MAX; d <<= 1) {
        int u = (t < NB_MAX && t >= d) ? sh[t - d] : 0;
        __syncthreads();
        if (t < NB_MAX) sh[t] += u;
        __syncthreads();
    }
    // sh[k] = inclusive prefix; exclusive offset for block k = sh[k-1] (0 for k=0)
    int gt = blockIdx.x * blockDim.x + t;

    // node part: write g_off for agg kernels
    if (gt < n) {
        int bidx = gt >> 10;
        int boff = (bidx > 0) ? sh[bidx - 1] : 0;
        g_off[gt] = g_sl[gt] + boff;
        if (gt == n - 1) g_off[n] = g_sl[gt] + boff + g_cnt[gt];
    }

    // edge part: scatter src ids
    int e = gt * 4;
    if (e + 3 < E) {
        int4 s  = *(const int4*)(ei + e);
        int4 d  = *(const int4*)(ei + E + e);
        int4 sl = *(const int4*)(g_slot + e);
        int bx = d.x >> 10, by = d.y >> 10, bz = d.z >> 10, bw = d.w >> 10;
        int ox = g_sl[d.x] + ((bx > 0) ? sh[bx - 1] : 0);
        int oy = g_sl[d.y] + ((by > 0) ? sh[by - 1] : 0);
        int oz = g_sl[d.z] + ((bz > 0) ? sh[bz - 1] : 0);
        int ow = g_sl[d.w] + ((bw > 0) ? sh[bw - 1] : 0);
        g_csr[ox + sl.x] = s.x;
        g_csr[oy + sl.y] = s.y;
        g_csr[oz + sl.z] = s.z;
        g_csr[ow + sl.w] = s.w;
    } else {
        for (; e < E; e++) {
            int d = ei[E + e];
            int b = d >> 10;
            int o = g_sl[d] + ((b > 0) ? sh[b - 1] : 0);
            g_csr[o + g_slot[e]] = ei[e];
        }
    }
}

// ---------------- fp16 tensor-core GEMM: g_h16[M,:] = dis[row] * (A @ W) ------
// 128-row tiles, 256 threads (8 warps: 4M x 2N), warp tile 32x64, mma.m16n8k16.
// K chunked by 64. dis computed inline from g_cnt (no scan dependency).
__global__ __launch_bounds__(256, 2)
void gemm_fp16_k(const float* __restrict__ Ax, const float* __restrict__ W,
                 int M, int use_ga)
{
    __shared__ __align__(16) __half2 As2[128][36];
    __shared__ __align__(16) __half2 Bs2[32][136];

    int tid  = threadIdx.x;
    int wid  = tid >> 5;
    int lane = tid & 31;
    int g    = lane >> 2;
    int tig  = lane & 3;
    int warp_m = wid & 3;
    int warp_n = wid >> 2;
    int row0 = blockIdx.x * 128;

    float acc[2][8][4];
#pragma unroll
    for (int mf = 0; mf < 2; mf++)
#pragma unroll
        for (int nf = 0; nf < 8; nf++)
#pragma unroll
            for (int i = 0; i < 4; i++) acc[mf][nf][i] = 0.f;

    for (int kb = 0; kb < 128; kb += 64) {
        if (use_ga) {
            const __half* A16 = g_a16;
#pragma unroll
            for (int l = 0; l < 4; l++) {
                int idx = tid + l * 256;
                int r  = idx >> 3;
                int c8 = idx & 7;
                int gr = row0 + r;
                if (gr > M - 1) gr = M - 1;
                float4 raw = *(const float4*)(A16 + (size_t)gr * 128 + kb + c8 * 8);
                *(float4*)(&As2[r][c8 * 4]) = raw;
            }
        } else {
#pragma unroll
            for (int l = 0; l < 8; l++) {
                int idx = tid + l * 256;
                int r  = idx >> 4;
                int c4 = idx & 15;
                int gr = row0 + r;
                if (gr > M - 1) gr = M - 1;
                float4 v = *(const float4*)(Ax + (size_t)gr * 128 + kb + c4 * 4);
                As2[r][c4 * 2]     = __floats2half2_rn(v.x, v.y);
                As2[r][c4 * 2 + 1] = __floats2half2_rn(v.z, v.w);
            }
        }
#pragma unroll
        for (int l = 0; l < 4; l++) {
            int idx = tid + l * 256;
            int r  = idx >> 5;
            int c4 = idx & 31;
            const float* w0 = W + (size_t)(kb + 2 * r) * 128 + c4 * 4;
            float4 v0 = *(const float4*)w0;
            float4 v1 = *(const float4*)(w0 + 128);
            __half2 p0 = __floats2half2_rn(v0.x, v1.x);
            __half2 p1 = __floats2half2_rn(v0.y, v1.y);
            __half2 p2 = __floats2half2_rn(v0.z, v1.z);
            __half2 p3 = __floats2half2_rn(v0.w, v1.w);
            __half2* d = &Bs2[r][c4 * 4];
            d[0] = p0; d[1] = p1; d[2] = p2; d[3] = p3;
        }
        __syncthreads();

#pragma unroll
        for (int ks = 0; ks < 4; ks++) {
            int k0 = ks * 8;
            unsigned a[2][4];
#pragma unroll
            for (int mf = 0; mf < 2; mf++) {
                int rb = warp_m * 32 + mf * 16 + g;
                a[mf][0] = *(unsigned*)&As2[rb][k0 + tig];
                a[mf][1] = *(unsigned*)&As2[rb + 8][k0 + tig];
                a[mf][2] = *(unsigned*)&As2[rb][k0 + tig + 4];
                a[mf][3] = *(unsigned*)&As2[rb + 8][k0 + tig + 4];
            }
            unsigned b[8][2];
#pragma unroll
            for (int nf = 0; nf < 8; nf++) {
                int cb = warp_n * 64 + nf * 8 + g;
                b[nf][0] = *(unsigned*)&Bs2[k0 + tig][cb];
                b[nf][1] = *(unsigned*)&Bs2[k0 + tig + 4][cb];
            }
#pragma unroll
            for (int mf = 0; mf < 2; mf++)
#pragma unroll
                for (int nf = 0; nf < 8; nf++) {
                    asm volatile(
                        "mma.sync.aligned.m16n8k16.row.col.f32.f16.f16.f32 "
                        "{%0,%1,%2,%3}, {%4,%5,%6,%7}, {%8,%9}, {%0,%1,%2,%3};"
                        : "+f"(acc[mf][nf][0]), "+f"(acc[mf][nf][1]),
                          "+f"(acc[mf][nf][2]), "+f"(acc[mf][nf][3])
                        : "r"(a[mf][0]), "r"(a[mf][1]), "r"(a[mf][2]), "r"(a[mf][3]),
                          "r"(b[nf][0]), "r"(b[nf][1]));
                }
        }
        __syncthreads();
    }

    // epilogue: scale by rsqrt(1+cnt[row]) computed inline, write fp16
#pragma unroll
    for (int mf = 0; mf < 2; mf++) {
        int rb = row0 + warp_m * 32 + mf * 16 + g;
        float d0 = (rb < M)     ? rsqrtf(1.0f + (float)g_cnt[rb])     : 0.f;
        float d1 = (rb + 8 < M) ? rsqrtf(1.0f + (float)g_cnt[rb + 8]) : 0.f;
#pragma unroll
        for (int nf = 0; nf < 8; nf++) {
            int col = warp_n * 64 + nf * 8 + tig * 2;
            if (rb < M) {
                __half2 v = __floats2half2_rn(d0 * acc[mf][nf][0], d0 * acc[mf][nf][1]);
                *(__half2*)(g_h16 + (size_t)rb * 128 + col) = v;
            }
            if (rb + 8 < M) {
                __half2 v = __floats2half2_rn(d1 * acc[mf][nf][2], d1 * acc[mf][nf][3]);
                *(__half2*)(g_h16 + (size_t)(rb + 8) * 128 + col) = v;
            }
        }
    }
}

// ---------------- aggregation: warp per node, pure gather+add ----------------
__global__ void agg128_k(const float* __restrict__ b, int M,
                         const float* __restrict__ W4)
{
    int w = (blockIdx.x * blockDim.x + threadIdx.x) >> 5;
    if (w >= M) return;
    int lane = threadIdx.x & 31;
    const __half* __restrict__ h = g_h16;
    int beg = g_off[w], end = g_off[w + 1];
    float dv = g_dis[w];

    float ax = 0.f, ay = 0.f, az = 0.f, aw = 0.f;
    int e = beg;
    for (; e < end && (e & 3); e++) {
        int s0 = g_csr[e];
        float4 h0 = h8_to_f4(((const float2*)(h + (size_t)s0 * 128))[lane]);
        ax += h0.x; ay += h0.y; az += h0.z; aw += h0.w;
    }
    for (; e + 8 <= end; e += 8) {
        int4 i0 = *(const int4*)(g_csr + e);
        int4 i1 = *(const int4*)(g_csr + e + 4);
        float2 r0 = ((const float2*)(h + (size_t)i0.x * 128))[lane];
        float2 r1 = ((const float2*)(h + (size_t)i0.y * 128))[lane];
        float2 r2 = ((const float2*)(h + (size_t)i0.z * 128))[lane];
        float2 r3 = ((const float2*)(h + (size_t)i0.w * 128))[lane];
        float2 r4 = ((const float2*)(h + (size_t)i1.x * 128))[lane];
        float2 r5 = ((const float2*)(h + (size_t)i1.y * 128))[lane];
        float2 r6 = ((const float2*)(h + (size_t)i1.z * 128))[lane];
        float2 r7 = ((const float2*)(h + (size_t)i1.w * 128))[lane];
        float4 p0 = pairsum_f4(r0, r1);
        float4 p1 = pairsum_f4(r2, r3);
        float4 p2 = pairsum_f4(r4, r5);
        float4 p3 = pairsum_f4(r6, r7);
        ax += (p0.x + p1.x) + (p2.x + p3.x);
        ay += (p0.y + p1.y) + (p2.y + p3.y);
        az += (p0.z + p1.z) + (p2.z + p3.z);
        aw += (p0.w + p1.w) + (p2.w + p3.w);
    }
    for (; e < end; e++) {
        int s0 = g_csr[e];
        float4 h0 = h8_to_f4(((const float2*)(h + (size_t)s0 * 128))[lane]);
        ax += h0.x; ay += h0.y; az += h0.z; aw += h0.w;
    }

    float4 hs = h8_to_f4(((const float2*)(h + (size_t)w * 128))[lane]);
    float4 bb = ((const float4*)b)[lane];
    float rx = fmaxf(dv * (ax + hs.x) + bb.x, 0.f);
    float ry = fmaxf(dv * (ay + hs.y) + bb.y, 0.f);
    float rz = fmaxf(dv * (az + hs.z) + bb.z, 0.f);
    float rw = fmaxf(dv * (aw + hs.w) + bb.w, 0.f);

    if (W4 == nullptr) {
        ((float2*)(g_a16 + (size_t)w * 128))[lane] = f4_to_h8(rx, ry, rz, rw);
    } else {
        float4 wv = ((const float4*)W4)[lane];
        float s = rx * wv.x + ry * wv.y + rz * wv.z + rw * wv.w;
#pragma unroll
        for (int o = 16; o; o >>= 1) s += __shfl_xor_sync(0xFFFFFFFFu, s, o);
        if (lane == 0) g_t[w] = dv * s;
    }
}

// warp per node: lanes gather edges in parallel, shfl reduce.
// also re-zeroes g_cnt for the next launch (graph replay invariant).
__global__ void final_agg_k(const float* __restrict__ b4, float* __restrict__ out, int M)
{
    int w = (blockIdx.x * blockDim.x + threadIdx.x) >> 5;
    if (w >= M) return;
    int lane = threadIdx.x & 31;
    int beg = g_off[w], end = g_off[w + 1];
    float s = 0.f;
    for (int e = beg + lane; e < end; e += 32) s += g_t[g_csr[e]];
#pragma unroll
    for (int o = 16; o; o >>= 1) s += __shfl_xor_sync(0xFFFFFFFFu, s, o);
    if (lane == 0) out[w] = g_dis[w] * (s + g_t[w]) + b4[0];
    if (lane == 1) g_cnt[w] = 0;   // leave zeroed for next launch
}

// ---------------- launch ----------------
extern "C" void kernel_launch(void* const* d_in, const int* in_sizes, int n_in,
                              void* d_out, int out_size)
{
    const float* x  = (const float*)d_in[0];
    const int*   ei = (const int*)d_in[1];
    const float* W1 = (const float*)d_in[2]; const float* b1 = (const float*)d_in[3];
    const float* W2 = (const float*)d_in[4]; const float* b2 = (const float*)d_in[5];
    const float* W3 = (const float*)d_in[6]; const float* b3 = (const float*)d_in[7];
    const float* W4 = (const float*)d_in[8]; const float* b4 = (const float*)d_in[9];

    int N = in_sizes[0] / 128;   // 50000
    int E = in_sizes[1] / 2;     // 1600000
    float* out = (float*)d_out;

    int nb = (N + SCAN_B - 1) / SCAN_B;

    static cudaStream_t s2 = nullptr;
    static cudaEvent_t ev_fork, ev_cnt, ev_csr;
    if (s2 == nullptr) {
        cudaStreamCreateWithFlags(&s2, cudaStreamNonBlocking);
        cudaEventCreateWithFlags(&ev_fork, cudaEventDisableTiming);
        cudaEventCreateWithFlags(&ev_cnt,  cudaEventDisableTiming);
        cudaEventCreateWithFlags(&ev_csr,  cudaEventDisableTiming);
    }

    // fork: graph preprocessing on s2 (g_cnt is already zero — invariant)
    cudaEventRecord(ev_fork, 0);
    cudaStreamWaitEvent(s2, ev_fork, 0);
    hist_dst_k<<<(E / 4 + 255) / 256, 256, 0, s2>>>(ei, E);
    cudaEventRecord(ev_cnt, s2);
    scan1_k   <<<nb, SCAN_B, 0, s2>>>(N);
    finalize_k<<<(E / 4 + 255) / 256, 256, 0, s2>>>(ei, E, N, nb);
    cudaEventRecord(ev_csr, s2);

    int gemm_blocks = (N + 127) / 128;          // 391
    int agg_blocks  = (N * 32 + 255) / 256;

    // GEMM-1 needs only g_cnt: overlaps scan1 + finalize on s2
    cudaStreamWaitEvent(0, ev_cnt, 0);
    gemm_fp16_k<<<gemm_blocks, 256>>>(x, W1, N, 0);
    cudaStreamWaitEvent(0, ev_csr, 0);
    agg128_k   <<<agg_blocks, 256>>>(b1, N, nullptr);

    gemm_fp16_k<<<gemm_blocks, 256>>>(x, W2, N, 1);
    agg128_k   <<<agg_blocks, 256>>>(b2, N, nullptr);

    gemm_fp16_k<<<gemm_blocks, 256>>>(x, W3, N, 1);
    agg128_k   <<<agg_blocks, 256>>>(b3, N, W4);

    final_agg_k<<<agg_blocks, 256>>>(b4, out, N);
}

// round 16
// speedup vs baseline: 1.0460x; 1.0231x over previous
#include <cuda_runtime.h>
#include <cuda_fp16.h>
#include <cstddef>

#define NN_MAX 50000
#define EE_MAX 1600000
#define SCAN_B 1024
#define NB_MAX 64

// GEMM dynamic smem layout (half2 units)
#define A_STRIDE 68                        // 64 data + 4 pad (4g mod 32 conflict-free)
#define B_STRIDE 136
#define A_SMEM_H2 (128 * A_STRIDE)         // 8704 half2 = 34816 B
#define B_SMEM_H2 (64 * B_STRIDE)          // 8704 half2 = 34816 B
#define GEMM_SMEM_BYTES ((A_SMEM_H2 + B_SMEM_H2) * 4)

// -------- scratch (device globals; no allocation allowed) --------
__device__ __align__(16) float  g_dis[NN_MAX];
__device__ int    g_cnt[NN_MAX];      // zeroed at END of each launch (final_agg_k)
__device__ int    g_off[NN_MAX + 1];
__device__ int    g_sl[NN_MAX];
__device__ int    g_bsum[NB_MAX];
__device__ __align__(16) int g_slot[EE_MAX];
__device__ __align__(16) int g_csr[EE_MAX];
__device__ __align__(16) __half g_h16[(size_t)NN_MAX * 128];  // post-GEMM, pre-scaled
__device__ __align__(16) __half g_a16[(size_t)NN_MAX * 128];  // post-agg activations
__device__ float  g_t[NN_MAX];

// ---------------- helpers ----------------
__device__ __forceinline__ float4 h8_to_f4(float2 raw) {
    __half2 ha = *reinterpret_cast<__half2*>(&raw.x);
    __half2 hb = *reinterpret_cast<__half2*>(&raw.y);
    float2 fa = __half22float2(ha), fb = __half22float2(hb);
    return make_float4(fa.x, fa.y, fb.x, fb.y);
}
__device__ __forceinline__ float2 f4_to_h8(float x, float y, float z, float w) {
    __half2 h0 = __floats2half2_rn(x, y), h1 = __floats2half2_rn(z, w);
    float2 o;
    o.x = *reinterpret_cast<float*>(&h0);
    o.y = *reinterpret_cast<float*>(&h1);
    return o;
}
__device__ __forceinline__ float4 pairsum_f4(float2 ra, float2 rb) {
    __half2 alo = *reinterpret_cast<__half2*>(&ra.x);
    __half2 ahi = *reinterpret_cast<__half2*>(&ra.y);
    __half2 blo = *reinterpret_cast<__half2*>(&rb.x);
    __half2 bhi = *reinterpret_cast<__half2*>(&rb.y);
    __half2 slo = __hadd2(alo, blo);
    __half2 shi = __hadd2(ahi, bhi);
    float2 fa = __half22float2(slo), fb = __half22float2(shi);
    return make_float4(fa.x, fa.y, fb.x, fb.y);
}

// ---------------- graph preprocessing ----------------
__global__ void hist_dst_k(const int* __restrict__ ei, int E) {
    int t = blockIdx.x * blockDim.x + threadIdx.x;
    int e = t * 4;
    if (e + 3 < E) {
        int4 d = *(const int4*)(ei + E + e);
        int p0 = atomicAdd(&g_cnt[d.x], 1);
        int p1 = atomicAdd(&g_cnt[d.y], 1);
        int p2 = atomicAdd(&g_cnt[d.z], 1);
        int p3 = atomicAdd(&g_cnt[d.w], 1);
        *(int4*)(g_slot + e) = make_int4(p0, p1, p2, p3);
    } else {
        for (; e < E; e++) g_slot[e] = atomicAdd(&g_cnt[ei[E + e]], 1);
    }
}

// block-local scan + per-block totals + dis (fused)
__global__ void scan1_k(int n) {
    __shared__ int sh[SCAN_B];
    int t = threadIdx.x;
    int i = blockIdx.x * SCAN_B + t;
    int v = (i < n) ? g_cnt[i] : 0;
    sh[t] = v;
    __syncthreads();
    for (int d = 1; d < SCAN_B; d <<= 1) {
        int u = (t >= d) ? sh[t - d] : 0;
        __syncthreads();
        sh[t] += u;
        __syncthreads();
    }
    if (i < n) {
        g_sl[i] = sh[t] - v;
        g_dis[i] = rsqrtf(1.0f + (float)v);
    }
    if (t == SCAN_B - 1) g_bsum[blockIdx.x] = sh[t];
}

// fused scan3 + build_csr
__global__ void finalize_k(const int* __restrict__ ei, int E, int n, int nb) {
    __shared__ int sh[NB_MAX];
    int t = threadIdx.x;
    if (t < NB_MAX) sh[t] = (t < nb) ? g_bsum[t] : 0;
    __syncthreads();
    for (int d = 1; d < NB_MAX; d <<= 1) {
        int u = (t < NB_MAX && t >= d) ? sh[t - d] : 0;
        __syncthreads();
        if (t < NB_MAX) sh[t] += u;
        __syncthreads();
    }
    int gt = blockIdx.x * blockDim.x + t;

    if (gt < n) {
        int bidx = gt >> 10;
        int boff = (bidx > 0) ? sh[bidx - 1] : 0;
        g_off[gt] = g_sl[gt] + boff;
        if (gt == n - 1) g_off[n] = g_sl[gt] + boff + g_cnt[gt];
    }

    int e = gt * 4;
    if (e + 3 < E) {
        int4 s  = *(const int4*)(ei + e);
        int4 d  = *(const int4*)(ei + E + e);
        int4 sl = *(const int4*)(g_slot + e);
        int bx = d.x >> 10, by = d.y >> 10, bz = d.z >> 10, bw = d.w >> 10;
        int ox = g_sl[d.x] + ((bx > 0) ? sh[bx - 1] : 0);
        int oy = g_sl[d.y] + ((by > 0) ? sh[by - 1] : 0);
        int oz = g_sl[d.z] + ((bz > 0) ? sh[bz - 1] : 0);
        int ow = g_sl[d.w] + ((bw > 0) ? sh[bw - 1] : 0);
        g_csr[ox + sl.x] = s.x;
        g_csr[oy + sl.y] = s.y;
        g_csr[oz + sl.z] = s.z;
        g_csr[ow + sl.w] = s.w;
    } else {
        for (; e < E; e++) {
            int d = ei[E + e];
            int b = d >> 10;
            int o = g_sl[d] + ((b > 0) ? sh[b - 1] : 0);
            g_csr[o + g_slot[e]] = ei[e];
        }
    }
}

// ---------------- fp16 tensor-core GEMM: g_h16[M,:] = dis[row] * (A @ W) ------
// 128-row tiles, 256 threads (8 warps: 4M x 2N), warp tile 32x64, mma.m16n8k16.
// SINGLE K=128 chunk in dynamic smem: one load phase (max MLP), ONE sync,
// 8 uninterrupted k16 MMA steps. dis computed inline from g_cnt.
__global__ __launch_bounds__(256, 2)
void gemm_fp16_k(const float* __restrict__ Ax, const float* __restrict__ W,
                 int M, int use_ga)
{
    extern __shared__ __half2 smem_h2[];
    __half2* As2 = smem_h2;                    // [128][A_STRIDE]
    __half2* Bs2 = smem_h2 + A_SMEM_H2;        // [64][B_STRIDE]

    int tid  = threadIdx.x;
    int wid  = tid >> 5;
    int lane = tid & 31;
    int g    = lane >> 2;
    int tig  = lane & 3;
    int warp_m = wid & 3;
    int warp_n = wid >> 2;
    int row0 = blockIdx.x * 128;

    float acc[2][8][4];
#pragma unroll
    for (int mf = 0; mf < 2; mf++)
#pragma unroll
        for (int nf = 0; nf < 8; nf++)
#pragma unroll
            for (int i = 0; i < 4; i++) acc[mf][nf][i] = 0.f;

    // ---- load phase: entire A tile (128x128) + entire W (128x128) ----
    if (use_ga) {
        // fp16 A: 128 rows x 16 8-half groups = 2048 float4, 8 passes
        const __half* A16 = g_a16;
#pragma unroll
        for (int l = 0; l < 8; l++) {
            int idx = tid + l * 256;
            int r  = idx >> 4;
            int c8 = idx & 15;
            int gr = row0 + r;
            if (gr > M - 1) gr = M - 1;
            float4 raw = *(const float4*)(A16 + (size_t)gr * 128 + c8 * 8);
            *(float4*)(&As2[r * A_STRIDE + c8 * 4]) = raw;
        }
    } else {
        // fp32 A: 128 rows x 32 float4 = 4096 tasks, 16 passes
#pragma unroll
        for (int l = 0; l < 16; l++) {
            int idx = tid + l * 256;
            int r  = idx >> 5;
            int c4 = idx & 31;
            int gr = row0 + r;
            if (gr > M - 1) gr = M - 1;
            float4 v = *(const float4*)(Ax + (size_t)gr * 128 + c4 * 4);
            As2[r * A_STRIDE + c4 * 2]     = __floats2half2_rn(v.x, v.y);
            As2[r * A_STRIDE + c4 * 2 + 1] = __floats2half2_rn(v.z, v.w);
        }
    }
    // W: 64 kpairs x 32 col-groups = 2048 tasks, 8 passes
#pragma unroll
    for (int l = 0; l < 8; l++) {
        int idx = tid + l * 256;
        int r  = idx >> 5;                    // kpair 0..63
        int c4 = idx & 31;
        const float* w0 = W + (size_t)(2 * r) * 128 + c4 * 4;
        float4 v0 = *(const float4*)w0;
        float4 v1 = *(const float4*)(w0 + 128);
        __half2 p0 = __floats2half2_rn(v0.x, v1.x);
        __half2 p1 = __floats2half2_rn(v0.y, v1.y);
        __half2 p2 = __floats2half2_rn(v0.z, v1.z);
        __half2 p3 = __floats2half2_rn(v0.w, v1.w);
        __half2* d = &Bs2[r * B_STRIDE + c4 * 4];
        d[0] = p0; d[1] = p1; d[2] = p2; d[3] = p3;
    }
    __syncthreads();

    // ---- MMA phase: 8 k16 steps, no syncs ----
#pragma unroll
    for (int ks = 0; ks < 8; ks++) {
        int k0 = ks * 8;                      // half2 units
        unsigned a[2][4];
#pragma unroll
        for (int mf = 0; mf < 2; mf++) {
            int rb = warp_m * 32 + mf * 16 + g;
            a[mf][0] = *(unsigned*)&As2[rb * A_STRIDE + k0 + tig];
            a[mf][1] = *(unsigned*)&As2[(rb + 8) * A_STRIDE + k0 + tig];
            a[mf][2] = *(unsigned*)&As2[rb * A_STRIDE + k0 + tig + 4];
            a[mf][3] = *(unsigned*)&As2[(rb + 8) * A_STRIDE + k0 + tig + 4];
        }
        unsigned b[8][2];
#pragma unroll
        for (int nf = 0; nf < 8; nf++) {
            int cb = warp_n * 64 + nf * 8 + g;
            b[nf][0] = *(unsigned*)&Bs2[(k0 + tig) * B_STRIDE + cb];
            b[nf][1] = *(unsigned*)&Bs2[(k0 + tig + 4) * B_STRIDE + cb];
        }
#pragma unroll
        for (int mf = 0; mf < 2; mf++)
#pragma unroll
            for (int nf = 0; nf < 8; nf++) {
                asm volatile(
                    "mma.sync.aligned.m16n8k16.row.col.f32.f16.f16.f32 "
                    "{%0,%1,%2,%3}, {%4,%5,%6,%7}, {%8,%9}, {%0,%1,%2,%3};"
                    : "+f"(acc[mf][nf][0]), "+f"(acc[mf][nf][1]),
                      "+f"(acc[mf][nf][2]), "+f"(acc[mf][nf][3])
                    : "r"(a[mf][0]), "r"(a[mf][1]), "r"(a[mf][2]), "r"(a[mf][3]),
                      "r"(b[nf][0]), "r"(b[nf][1]));
            }
    }

    // epilogue: scale by rsqrt(1+cnt[row]) computed inline, write fp16
#pragma unroll
    for (int mf = 0; mf < 2; mf++) {
        int rb = row0 + warp_m * 32 + mf * 16 + g;
        float d0 = (rb < M)     ? rsqrtf(1.0f + (float)g_cnt[rb])     : 0.f;
        float d1 = (rb + 8 < M) ? rsqrtf(1.0f + (float)g_cnt[rb + 8]) : 0.f;
#pragma unroll
        for (int nf = 0; nf < 8; nf++) {
            int col = warp_n * 64 + nf * 8 + tig * 2;
            if (rb < M) {
                __half2 v = __floats2half2_rn(d0 * acc[mf][nf][0], d0 * acc[mf][nf][1]);
                *(__half2*)(g_h16 + (size_t)rb * 128 + col) = v;
            }
            if (rb + 8 < M) {
                __half2 v = __floats2half2_rn(d1 * acc[mf][nf][2], d1 * acc[mf][nf][3]);
                *(__half2*)(g_h16 + (size_t)(rb + 8) * 128 + col) = v;
            }
        }
    }
}

// ---------------- aggregation: warp per node, pure gather+add ----------------
__global__ void agg128_k(const float* __restrict__ b, int M,
                         const float* __restrict__ W4)
{
    int w = (blockIdx.x * blockDim.x + threadIdx.x) >> 5;
    if (w >= M) return;
    int lane = threadIdx.x & 31;
    const __half* __restrict__ h = g_h16;
    int beg = g_off[w], end = g_off[w + 1];
    float dv = g_dis[w];

    float ax = 0.f, ay = 0.f, az = 0.f, aw = 0.f;
    int e = beg;
    for (; e < end && (e & 3); e++) {
        int s0 = g_csr[e];
        float4 h0 = h8_to_f4(((const float2*)(h + (size_t)s0 * 128))[lane]);
        ax += h0.x; ay += h0.y; az += h0.z; aw += h0.w;
    }
    for (; e + 8 <= end; e += 8) {
        int4 i0 = *(const int4*)(g_csr + e);
        int4 i1 = *(const int4*)(g_csr + e + 4);
        float2 r0 = ((const float2*)(h + (size_t)i0.x * 128))[lane];
        float2 r1 = ((const float2*)(h + (size_t)i0.y * 128))[lane];
        float2 r2 = ((const float2*)(h + (size_t)i0.z * 128))[lane];
        float2 r3 = ((const float2*)(h + (size_t)i0.w * 128))[lane];
        float2 r4 = ((const float2*)(h + (size_t)i1.x * 128))[lane];
        float2 r5 = ((const float2*)(h + (size_t)i1.y * 128))[lane];
        float2 r6 = ((const float2*)(h + (size_t)i1.z * 128))[lane];
        float2 r7 = ((const float2*)(h + (size_t)i1.w * 128))[lane];
        float4 p0 = pairsum_f4(r0, r1);
        float4 p1 = pairsum_f4(r2, r3);
        float4 p2 = pairsum_f4(r4, r5);
        float4 p3 = pairsum_f4(r6, r7);
        ax += (p0.x + p1.x) + (p2.x + p3.x);
        ay += (p0.y + p1.y) + (p2.y + p3.y);
        az += (p0.z + p1.z) + (p2.z + p3.z);
        aw += (p0.w + p1.w) + (p2.w + p3.w);
    }
    for (; e < end; e++) {
        int s0 = g_csr[e];
        float4 h0 = h8_to_f4(((const float2*)(h + (size_t)s0 * 128))[lane]);
        ax += h0.x; ay += h0.y; az += h0.z; aw += h0.w;
    }

    float4 hs = h8_to_f4(((const float2*)(h + (size_t)w * 128))[lane]);
    float4 bb = ((const float4*)b)[lane];
    float rx = fmaxf(dv * (ax + hs.x) + bb.x, 0.f);
    float ry = fmaxf(dv * (ay + hs.y) + bb.y, 0.f);
    float rz = fmaxf(dv * (az + hs.z) + bb.z, 0.f);
    float rw = fmaxf(dv * (aw + hs.w) + bb.w, 0.f);

    if (W4 == nullptr) {
        ((float2*)(g_a16 + (size_t)w * 128))[lane] = f4_to_h8(rx, ry, rz, rw);
    } else {
        float4 wv = ((const float4*)W4)[lane];
        float s = rx * wv.x + ry * wv.y + rz * wv.z + rw * wv.w;
#pragma unroll
        for (int o = 16; o; o >>= 1) s += __shfl_xor_sync(0xFFFFFFFFu, s, o);
        if (lane == 0) g_t[w] = dv * s;
    }
}

// warp per node: lanes gather edges in parallel, shfl reduce.
// also re-zeroes g_cnt for the next launch (graph replay invariant).
__global__ void final_agg_k(const float* __restrict__ b4, float* __restrict__ out, int M)
{
    int w = (blockIdx.x * blockDim.x + threadIdx.x) >> 5;
    if (w >= M) return;
    int lane = threadIdx.x & 31;
    int beg = g_off[w], end = g_off[w + 1];
    float s = 0.f;
    for (int e = beg + lane; e < end; e += 32) s += g_t[g_csr[e]];
#pragma unroll
    for (int o = 16; o; o >>= 1) s += __shfl_xor_sync(0xFFFFFFFFu, s, o);
    if (lane == 0) out[w] = g_dis[w] * (s + g_t[w]) + b4[0];
    if (lane == 1) g_cnt[w] = 0;   // leave zeroed for next launch
}

// ---------------- launch ----------------
extern "C" void kernel_launch(void* const* d_in, const int* in_sizes, int n_in,
                              void* d_out, int out_size)
{
    const float* x  = (const float*)d_in[0];
    const int*   ei = (const int*)d_in[1];
    const float* W1 = (const float*)d_in[2]; const float* b1 = (const float*)d_in[3];
    const float* W2 = (const float*)d_in[4]; const float* b2 = (const float*)d_in[5];
    const float* W3 = (const float*)d_in[6]; const float* b3 = (const float*)d_in[7];
    const float* W4 = (const float*)d_in[8]; const float* b4 = (const float*)d_in[9];

    int N = in_sizes[0] / 128;   // 50000
    int E = in_sizes[1] / 2;     // 1600000
    float* out = (float*)d_out;

    int nb = (N + SCAN_B - 1) / SCAN_B;

    static cudaStream_t s2 = nullptr;
    static cudaEvent_t ev_fork, ev_cnt, ev_csr;
    if (s2 == nullptr) {
        cudaStreamCreateWithFlags(&s2, cudaStreamNonBlocking);
        cudaEventCreateWithFlags(&ev_fork, cudaEventDisableTiming);
        cudaEventCreateWithFlags(&ev_cnt,  cudaEventDisableTiming);
        cudaEventCreateWithFlags(&ev_csr,  cudaEventDisableTiming);
        cudaFuncSetAttribute(gemm_fp16_k,
                             cudaFuncAttributeMaxDynamicSharedMemorySize,
                             GEMM_SMEM_BYTES);
    }

    // fork: graph preprocessing on s2 (g_cnt is already zero — invariant)
    cudaEventRecord(ev_fork, 0);
    cudaStreamWaitEvent(s2, ev_fork, 0);
    hist_dst_k<<<(E / 4 + 255) / 256, 256, 0, s2>>>(ei, E);
    cudaEventRecord(ev_cnt, s2);
    scan1_k   <<<nb, SCAN_B, 0, s2>>>(N);
    finalize_k<<<(E / 4 + 255) / 256, 256, 0, s2>>>(ei, E, N, nb);
    cudaEventRecord(ev_csr, s2);

    int gemm_blocks = (N + 127) / 128;          // 391
    int agg_blocks  = (N * 32 + 255) / 256;

    // GEMM-1 needs only g_cnt: overlaps scan1 + finalize on s2
    cudaStreamWaitEvent(0, ev_cnt, 0);
    gemm_fp16_k<<<gemm_blocks, 256, GEMM_SMEM_BYTES>>>(x, W1, N, 0);
    cudaStreamWaitEvent(0, ev_csr, 0);
    agg128_k   <<<agg_blocks, 256>>>(b1, N, nullptr);

    gemm_fp16_k<<<gemm_blocks, 256, GEMM_SMEM_BYTES>>>(x, W2, N, 1);
    agg128_k   <<<agg_blocks, 256>>>(b2, N, nullptr);

    gemm_fp16_k<<<gemm_blocks, 256, GEMM_SMEM_BYTES>>>(x, W3, N, 1);
    agg128_k   <<<agg_blocks, 256>>>(b3, N, W4);

    final_agg_k<<<agg_blocks, 256>>>(b4, out, N);
}